// round 10
// baseline (speedup 1.0000x reference)
#include <cuda_runtime.h>
#include <math.h>

#define N_NET 16
#define HID   32

// Fused: warps 0-15 of every block redundantly evaluate the 16 tiny MLPs on
// s[0]; after one barrier, all 32 warps derive the softmax and store.
// Grid 128 x 1024: 128*1024 threads * 1 float4 = 131072 float4 = 262144*2 floats.
__global__ __launch_bounds__(1024, 1)
void controller_fused_kernel(const float* __restrict__ s,
                             const float* __restrict__ W1,
                             const float* __restrict__ b1,
                             const float* __restrict__ W2,
                             const float* __restrict__ b2,
                             const float* __restrict__ W3,
                             const float* __restrict__ b3,
                             float4* __restrict__ out,
                             int n_vec4)
{
    __shared__ __align__(16) float smem_m[N_NET];

    const int tid  = threadIdx.x;
    const int wid  = tid >> 5;
    const int lane = tid & 31;

    if (wid < N_NET) {
        const int k = wid;                       // network id = warp id
        const float x = s[k & 3];

        // Layer 1
        const float h1 = fmaxf(fmaf(x, W1[k * HID + lane], b1[k * HID + lane]), 0.0f);

        // Layer 2: 4 independent accumulators (chain depth 8), coalesced W2 loads.
        const float* W2k = W2 + k * HID * HID + lane;
        float a0 = b2[k * HID + lane], a1 = 0.0f, a2 = 0.0f, a3 = 0.0f;
        #pragma unroll
        for (int i = 0; i < HID; i += 4) {
            const float v0 = __shfl_sync(0xFFFFFFFFu, h1, i + 0);
            const float v1 = __shfl_sync(0xFFFFFFFFu, h1, i + 1);
            const float v2 = __shfl_sync(0xFFFFFFFFu, h1, i + 2);
            const float v3 = __shfl_sync(0xFFFFFFFFu, h1, i + 3);
            a0 = fmaf(v0, W2k[(i + 0) * HID], a0);
            a1 = fmaf(v1, W2k[(i + 1) * HID], a1);
            a2 = fmaf(v2, W2k[(i + 2) * HID], a2);
            a3 = fmaf(v3, W2k[(i + 3) * HID], a3);
        }
        const float h2 = fmaxf((a0 + a1) + (a2 + a3), 0.0f);

        // Layer 3: fixed-point s15.16 warp sum in ONE redux.sync.add.s32
        // (|partial| <~ 8, sum <~ 50: no overflow; quant err ~2e-4 abs in t,
        //  ~1e-5 in final output — tolerance is 1e-3).
        const float partial = h2 * W3[k * HID + lane];
        const int   pi      = __float2int_rn(partial * 65536.0f);
        int tsum;
        asm volatile("redux.sync.add.s32 %0, %1, 0xffffffff;"
                     : "=r"(tsum) : "r"(pi));

        if (lane == 0) {
            const float t = (float)tsum * (1.0f / 65536.0f);
            const float z = t + b3[k];
            smem_m[k] = __fdividef(1.0f, 1.0f + __expf(-z));   // fast sigmoid
        }
    }
    __syncthreads();

    // ---- epilogue (all 32 warps): 4x LDS.128 instead of 16 scalar LDS ----
    const float4* mv = (const float4*)smem_m;
    const float4 m0 = mv[0], m1 = mv[1];   // networks 0..7  (action 0)
    const float4 m2 = mv[2], m3 = mv[3];   // networks 8..15 (action 1)
    const float s0 = ((m0.x + m0.y) + (m0.z + m0.w)) + ((m1.x + m1.y) + (m1.z + m1.w));
    const float s1 = ((m2.x + m2.y) + (m2.z + m2.w)) + ((m3.x + m3.y) + (m3.z + m3.w));
    // means + 2-way softmax as logistic; sums in (0,8) so exp is safe.
    const float d  = (s1 - s0) * 0.125f;
    const float p0 = __fdividef(1.0f, 1.0f + __expf(d));
    const float p1 = 1.0f - p0;
    const float4 v = make_float4(p0, p1, p0, p1);

    // ---- fill: exactly one float4 per thread, fully coalesced ----
    const int idx = blockIdx.x * 1024 + tid;
    if (idx < n_vec4) out[idx] = v;
}

extern "C" void kernel_launch(void* const* d_in, const int* in_sizes, int n_in,
                              void* d_out, int out_size)
{
    const float* s  = (const float*)d_in[0];
    const float* W1 = (const float*)d_in[1];
    const float* b1 = (const float*)d_in[2];
    const float* W2 = (const float*)d_in[3];
    const float* b2 = (const float*)d_in[4];
    const float* W3 = (const float*)d_in[5];
    const float* b3 = (const float*)d_in[6];

    // out_size = B*2 floats. For B=262144: n_vec4=131072 -> 128 blocks exactly.
    const int n_vec4 = out_size / 4;
    const int blocks = (n_vec4 + 1023) / 1024;   // 1024 threads, 1 float4 each

    controller_fused_kernel<<<blocks, 1024>>>(s, W1, b1, W2, b2, W3, b3,
                                              (float4*)d_out, n_vec4);
}